// round 1
// baseline (speedup 1.0000x reference)
#include <cuda_runtime.h>

#define N_NODES 100000
#define IN_DIM 512
#define HIDDEN 16
#define OUT_DIM 64

// ---------------- device scratch (no allocations allowed) ----------------
__device__ __align__(16) float g_z[(size_t)N_NODES * HIDDEN];   // x@W1, pre-scaled by dinv
__device__ __align__(16) float g_h[(size_t)N_NODES * HIDDEN];   // agg1 -> h1 (pre-scaled)
__device__ __align__(16) float g_a2[(size_t)N_NODES * HIDDEN];  // agg2
__device__ float g_deg[N_NODES];
__device__ float g_dinv[N_NODES];

// ---------------- helpers ----------------
__device__ __forceinline__ unsigned long long fma2(unsigned long long a,
                                                   unsigned long long b,
                                                   unsigned long long c) {
    unsigned long long d;
    asm("fma.rn.f32x2 %0, %1, %2, %3;" : "=l"(d) : "l"(a), "l"(b), "l"(c));
    return d;
}
__device__ __forceinline__ unsigned long long dup2(float v) {
    unsigned long long d;
    asm("mov.b64 %0, {%1, %2};" : "=l"(d) : "f"(v), "f"(v));
    return d;
}
__device__ __forceinline__ void red_add_v4(float* p, float a, float b, float c, float d) {
    asm volatile("red.global.add.v4.f32 [%0], {%1, %2, %3, %4};"
                 :: "l"(p), "f"(a), "f"(b), "f"(c), "f"(d) : "memory");
}
__device__ __forceinline__ void red_add_f32(float* p, float v) {
    asm volatile("red.global.add.f32 [%0], %1;" :: "l"(p), "f"(v) : "memory");
}

// ---------------- kernels ----------------

// zero agg buffers, deg = 1 (self loop)
__global__ void k_init() {
    int t = blockIdx.x * blockDim.x + threadIdx.x;
    float4 z4 = make_float4(0.f, 0.f, 0.f, 0.f);
    if (t < N_NODES * 4) {
        ((float4*)g_h)[t] = z4;
        ((float4*)g_a2)[t] = z4;
    }
    if (t < N_NODES) g_deg[t] = 1.0f;
}

__global__ void k_deg(const int* __restrict__ dst, int E) {
    int e = blockIdx.x * blockDim.x + threadIdx.x;
    if (e >= E) return;
    int d = __ldg(dst + e);
    red_add_f32(&g_deg[d], 1.0f);
}

__global__ void k_dinv() {
    int i = blockIdx.x * blockDim.x + threadIdx.x;
    if (i < N_NODES) g_dinv[i] = rsqrtf(g_deg[i]);
}

// z = (x @ W1) * dinv[row]   (pre-scale by dinv[src] for the scatter)
// 256 threads/block, 2 rows/thread -> 512 rows/block. W1 (32KB) in smem.
// f32x2 packed FMAs: 16 output cols = 8 f32x2 accumulators per row.
__global__ __launch_bounds__(256) void k_gemm1(const float* __restrict__ x,
                                               const float* __restrict__ W1) {
    __shared__ __align__(16) float ws[IN_DIM * HIDDEN];  // 32 KB
    {
        const float4* w4 = (const float4*)W1;
        float4* s4 = (float4*)ws;
#pragma unroll
        for (int i = 0; i < (IN_DIM * HIDDEN / 4) / 256; i++)
            s4[threadIdx.x + i * 256] = w4[threadIdx.x + i * 256];
    }
    __syncthreads();

    long long r0 = (long long)blockIdx.x * 512 + threadIdx.x * 2;
    long long a0 = (r0 < N_NODES) ? r0 : 0;
    long long a1 = (r0 + 1 < N_NODES) ? r0 + 1 : 0;
    const float4* x0 = (const float4*)(x + a0 * IN_DIM);
    const float4* x1 = (const float4*)(x + a1 * IN_DIM);

    unsigned long long acc0[8], acc1[8];
#pragma unroll
    for (int i = 0; i < 8; i++) { acc0[i] = 0ull; acc1[i] = 0ull; }

    const ulonglong2* wsp = (const ulonglong2*)ws;  // row k = 4 x ulonglong2

#pragma unroll 2
    for (int q = 0; q < IN_DIM / 4; q++) {
        float4 xa = x0[q];
        float4 xb = x1[q];
        const float* fa = (const float*)&xa;
        const float* fb = (const float*)&xb;
#pragma unroll
        for (int j = 0; j < 4; j++) {
            unsigned long long d0 = dup2(fa[j]);
            unsigned long long d1 = dup2(fb[j]);
#pragma unroll
            for (int c = 0; c < 4; c++) {
                ulonglong2 wv = wsp[(q * 4 + j) * 4 + c];
                acc0[2 * c]     = fma2(d0, wv.x, acc0[2 * c]);
                acc0[2 * c + 1] = fma2(d0, wv.y, acc0[2 * c + 1]);
                acc1[2 * c]     = fma2(d1, wv.x, acc1[2 * c]);
                acc1[2 * c + 1] = fma2(d1, wv.y, acc1[2 * c + 1]);
            }
        }
    }

    if (r0 < N_NODES) {
        float dv = g_dinv[r0];
        float2* zo = (float2*)(g_z + r0 * HIDDEN);
#pragma unroll
        for (int i = 0; i < 8; i++) {
            float2 p = *(float2*)&acc0[i];
            p.x *= dv; p.y *= dv;
            zo[i] = p;
        }
    }
    if (r0 + 1 < N_NODES) {
        float dv = g_dinv[r0 + 1];
        float2* zo = (float2*)(g_z + (r0 + 1) * HIDDEN);
#pragma unroll
        for (int i = 0; i < 8; i++) {
            float2 p = *(float2*)&acc1[i];
            p.x *= dv; p.y *= dv;
            zo[i] = p;
        }
    }
}

// edge scatter: out[dst] += vals[src] * dinv[dst]   (vals pre-scaled by dinv[src])
template <int LAYER>
__global__ __launch_bounds__(256) void k_scatter(const int* __restrict__ src,
                                                 const int* __restrict__ dst, int E) {
    int e = blockIdx.x * blockDim.x + threadIdx.x;
    if (e >= E) return;
    int s = __ldg(src + e);
    int d = __ldg(dst + e);
    float w = __ldg(&g_dinv[d]);
    const float* vals = (LAYER == 0) ? g_z : g_h;
    float* out = (LAYER == 0) ? g_h : g_a2;
    const float4* v4 = (const float4*)(vals + (size_t)s * HIDDEN);
    float* o = out + (size_t)d * HIDDEN;
#pragma unroll
    for (int j = 0; j < 4; j++) {
        float4 v = v4[j];
        red_add_v4(o + j * 4, v.x * w, v.y * w, v.z * w, v.w * w);
    }
}

// h1 = relu(agg1 + z*dinv + b1); store pre-scaled: g_h = h1 * dinv
__global__ void k_h1(const float* __restrict__ b1) {
    int t = blockIdx.x * blockDim.x + threadIdx.x;
    if (t >= N_NODES * 4) return;
    int i = t >> 2;
    int j = t & 3;
    float di = g_dinv[i];
    float4 a = ((const float4*)g_h)[t];
    float4 zz = ((const float4*)g_z)[t];
    float4 bb = __ldg((const float4*)b1 + j);
    float4 r;
    r.x = fmaxf(fmaf(zz.x, di, a.x) + bb.x, 0.f) * di;
    r.y = fmaxf(fmaf(zz.y, di, a.y) + bb.y, 0.f) * di;
    r.z = fmaxf(fmaf(zz.z, di, a.z) + bb.z, 0.f) * di;
    r.w = fmaxf(fmaf(zz.w, di, a.w) + bb.w, 0.f) * di;
    ((float4*)g_h)[t] = r;
}

// out = (agg2 + h1s*dinv) @ W2 + b2      (h1s = h1*dinv, so h1s*dinv = h1*dinv^2)
// 4 threads per row, each computes 16 output cols. W2 (4KB) in smem.
__global__ __launch_bounds__(256) void k_gemm2(const float* __restrict__ W2,
                                               const float* __restrict__ b2,
                                               float* __restrict__ out) {
    __shared__ __align__(16) float ws[HIDDEN * OUT_DIM];  // 1024 floats
    ((float4*)ws)[threadIdx.x] = ((const float4*)W2)[threadIdx.x];  // 256 float4
    __syncthreads();

    int gid = blockIdx.x * 256 + threadIdx.x;
    int r = gid >> 2;
    int cg = gid & 3;
    if (r >= N_NODES) return;

    float di = g_dinv[r];
    float hk[HIDDEN];
    const float4* A = (const float4*)(g_a2 + (size_t)r * HIDDEN);
    const float4* H = (const float4*)(g_h + (size_t)r * HIDDEN);
#pragma unroll
    for (int q = 0; q < 4; q++) {
        float4 a = A[q];
        float4 h = H[q];
        hk[4 * q + 0] = fmaf(h.x, di, a.x);
        hk[4 * q + 1] = fmaf(h.y, di, a.y);
        hk[4 * q + 2] = fmaf(h.z, di, a.z);
        hk[4 * q + 3] = fmaf(h.w, di, a.w);
    }

    float4 acc[4];
#pragma unroll
    for (int q = 0; q < 4; q++) acc[q] = make_float4(0.f, 0.f, 0.f, 0.f);

#pragma unroll
    for (int k = 0; k < HIDDEN; k++) {
        float xv = hk[k];
        const float4* wr = (const float4*)(ws + k * OUT_DIM + cg * 16);
#pragma unroll
        for (int q = 0; q < 4; q++) {
            float4 w = wr[q];
            acc[q].x = fmaf(xv, w.x, acc[q].x);
            acc[q].y = fmaf(xv, w.y, acc[q].y);
            acc[q].z = fmaf(xv, w.z, acc[q].z);
            acc[q].w = fmaf(xv, w.w, acc[q].w);
        }
    }

    const float4* bb = (const float4*)b2 + cg * 4;
    float4* O = (float4*)(out + (size_t)r * OUT_DIM) + cg * 4;
#pragma unroll
    for (int q = 0; q < 4; q++) {
        float4 b = __ldg(bb + q);
        O[q] = make_float4(acc[q].x + b.x, acc[q].y + b.y,
                           acc[q].z + b.z, acc[q].w + b.w);
    }
}

// ---------------- launch ----------------
extern "C" void kernel_launch(void* const* d_in, const int* in_sizes, int n_in,
                              void* d_out, int out_size) {
    // Identify inputs by element count (all distinct), robust to ordering.
    const float* x = nullptr;
    const float* W1 = nullptr;
    const float* b1 = nullptr;
    const float* W2 = nullptr;
    const float* b2 = nullptr;
    const int* ei = nullptr;
    int E = 0;
    for (int i = 0; i < n_in; i++) {
        long long sz = in_sizes[i];
        if (sz == (long long)N_NODES * IN_DIM)      x  = (const float*)d_in[i];
        else if (sz == IN_DIM * HIDDEN)             W1 = (const float*)d_in[i];
        else if (sz == HIDDEN)                      b1 = (const float*)d_in[i];
        else if (sz == HIDDEN * OUT_DIM)            W2 = (const float*)d_in[i];
        else if (sz == OUT_DIM)                     b2 = (const float*)d_in[i];
        else { ei = (const int*)d_in[i]; E = (int)(sz / 2); }
    }
    const int* src = ei;
    const int* dst = ei + E;
    float* out = (float*)d_out;

    const int TB = 256;
    int grid_n4 = (N_NODES * 4 + TB - 1) / TB;
    int grid_n  = (N_NODES + TB - 1) / TB;
    int grid_e  = (E + TB - 1) / TB;
    int grid_g1 = (N_NODES + 511) / 512;

    k_init<<<grid_n4, TB>>>();
    k_deg<<<grid_e, TB>>>(dst, E);
    k_dinv<<<grid_n, TB>>>();
    k_gemm1<<<grid_g1, TB>>>(x, W1);
    k_scatter<0><<<grid_e, TB>>>(src, dst, E);
    k_h1<<<grid_n4, TB>>>(b1);
    k_scatter<1><<<grid_e, TB>>>(src, dst, E);
    k_gemm2<<<grid_n4, TB>>>(W2, b2, out);
}

// round 3
// speedup vs baseline: 1.0537x; 1.0537x over previous
#include <cuda_runtime.h>

#define N_NODES 100000
#define IN_DIM 512
#define HIDDEN 16
#define OUT_DIM 64

// ---------------- device scratch (no allocations allowed) ----------------
__device__ __align__(16) float g_z[(size_t)N_NODES * HIDDEN];   // x@W1, pre-scaled by dinv[src]
__device__ __align__(16) float g_h[(size_t)N_NODES * HIDDEN];   // agg1 -> h1 (pre-scaled)
__device__ __align__(16) float g_a2[(size_t)N_NODES * HIDDEN];  // agg2
__device__ float g_deg[N_NODES];
__device__ float g_dinv[N_NODES];

// ---------------- helpers ----------------
__device__ __forceinline__ unsigned long long fma2(unsigned long long a,
                                                   unsigned long long b,
                                                   unsigned long long c) {
    unsigned long long d;
    asm("fma.rn.f32x2 %0, %1, %2, %3;" : "=l"(d) : "l"(a), "l"(b), "l"(c));
    return d;
}
__device__ __forceinline__ unsigned long long dup2(float v) {
    unsigned long long d;
    asm("mov.b64 %0, {%1, %2};" : "=l"(d) : "f"(v), "f"(v));
    return d;
}
__device__ __forceinline__ void red_add_v4(float* p, float a, float b, float c, float d) {
    asm volatile("red.global.add.v4.f32 [%0], {%1, %2, %3, %4};"
                 :: "l"(p), "f"(a), "f"(b), "f"(c), "f"(d) : "memory");
}
__device__ __forceinline__ void red_add_f32(float* p, float v) {
    asm volatile("red.global.add.f32 [%0], %1;" :: "l"(p), "f"(v) : "memory");
}

// ---------------- kernels ----------------

// zero agg buffers, deg = 1 (self loop)
__global__ void k_init() {
    int t = blockIdx.x * blockDim.x + threadIdx.x;
    float4 z4 = make_float4(0.f, 0.f, 0.f, 0.f);
    if (t < N_NODES * 4) {
        ((float4*)g_h)[t] = z4;
        ((float4*)g_a2)[t] = z4;
    }
    if (t < N_NODES) g_deg[t] = 1.0f;
}

// 2 edges per thread (paired); tail handled by a guarded scalar pass
__global__ void k_deg(const int* __restrict__ dst, int E2, int E) {
    int t = blockIdx.x * blockDim.x + threadIdx.x;
    if (t < E2) {
        int2 d = __ldg((const int2*)dst + t);
        red_add_f32(&g_deg[d.x], 1.0f);
        red_add_f32(&g_deg[d.y], 1.0f);
    } else if (t == E2 && (E & 1)) {
        red_add_f32(&g_deg[__ldg(dst + E - 1)], 1.0f);
    }
}

__global__ void k_dinv() {
    int i = blockIdx.x * blockDim.x + threadIdx.x;
    if (i < N_NODES) g_dinv[i] = rsqrtf(g_deg[i]);
}

// z = (x @ W1) * dinv[row]   (pre-scale by dinv[src] for the scatter)
// 128 threads/block, 1 row/thread -> 782 blocks. W1 (32KB) in smem.
// 8-deep float4 prefetch for MLP; f32x2 packed FMAs (8 accumulators).
__global__ __launch_bounds__(128) void k_gemm1(const float* __restrict__ x,
                                               const float* __restrict__ W1) {
    __shared__ __align__(16) float ws[IN_DIM * HIDDEN];  // 32 KB
    {
        const float4* w4 = (const float4*)W1;
        float4* s4 = (float4*)ws;
#pragma unroll
        for (int i = 0; i < (IN_DIM * HIDDEN / 4) / 128; i++)
            s4[threadIdx.x + i * 128] = w4[threadIdx.x + i * 128];
    }
    __syncthreads();

    long long r = (long long)blockIdx.x * 128 + threadIdx.x;
    long long ra = (r < N_NODES) ? r : 0;
    const float4* x0 = (const float4*)(x + ra * IN_DIM);

    unsigned long long acc[8];
#pragma unroll
    for (int i = 0; i < 8; i++) acc[i] = 0ull;

    const ulonglong2* wsp = (const ulonglong2*)ws;  // row k = 4 x ulonglong2

#pragma unroll 1
    for (int q0 = 0; q0 < IN_DIM / 4; q0 += 8) {
        float4 buf[8];
#pragma unroll
        for (int i = 0; i < 8; i++) buf[i] = x0[q0 + i];
#pragma unroll
        for (int i = 0; i < 8; i++) {
            const float* f = (const float*)&buf[i];
#pragma unroll
            for (int j = 0; j < 4; j++) {
                unsigned long long d0 = dup2(f[j]);
                int k = (q0 + i) * 4 + j;
#pragma unroll
                for (int c = 0; c < 4; c++) {
                    ulonglong2 wv = wsp[k * 4 + c];
                    acc[2 * c]     = fma2(d0, wv.x, acc[2 * c]);
                    acc[2 * c + 1] = fma2(d0, wv.y, acc[2 * c + 1]);
                }
            }
        }
    }

    if (r < N_NODES) {
        float dv = g_dinv[r];
        float2* zo = (float2*)(g_z + r * HIDDEN);
#pragma unroll
        for (int i = 0; i < 8; i++) {
            float2 p = *(float2*)&acc[i];
            p.x *= dv; p.y *= dv;
            zo[i] = p;
        }
    }
}

// edge scatter: out[dst] += vals[src]   (vals pre-scaled by dinv[src];
// dinv[dst] folded into the following per-node pass). 2 edges/thread.
template <int LAYER>
__global__ __launch_bounds__(256) void k_scatter(const int* __restrict__ src,
                                                 const int* __restrict__ dst,
                                                 int E2, int E) {
    int t = blockIdx.x * blockDim.x + threadIdx.x;
    const float* vals = (LAYER == 0) ? g_z : g_h;
    float* out = (LAYER == 0) ? g_h : g_a2;

    if (t < E2) {
        int2 s = __ldg((const int2*)src + t);
        int2 d = __ldg((const int2*)dst + t);

        const float4* va = (const float4*)(vals + (size_t)s.x * HIDDEN);
        const float4* vb = (const float4*)(vals + (size_t)s.y * HIDDEN);
        float4 a0 = va[0], a1 = va[1], a2 = va[2], a3 = va[3];
        float4 b0 = vb[0], b1 = vb[1], b2 = vb[2], b3 = vb[3];

        float* oa = out + (size_t)d.x * HIDDEN;
        float* ob = out + (size_t)d.y * HIDDEN;
        red_add_v4(oa + 0,  a0.x, a0.y, a0.z, a0.w);
        red_add_v4(oa + 4,  a1.x, a1.y, a1.z, a1.w);
        red_add_v4(oa + 8,  a2.x, a2.y, a2.z, a2.w);
        red_add_v4(oa + 12, a3.x, a3.y, a3.z, a3.w);
        red_add_v4(ob + 0,  b0.x, b0.y, b0.z, b0.w);
        red_add_v4(ob + 4,  b1.x, b1.y, b1.z, b1.w);
        red_add_v4(ob + 8,  b2.x, b2.y, b2.z, b2.w);
        red_add_v4(ob + 12, b3.x, b3.y, b3.z, b3.w);
    } else if (t == E2 && (E & 1)) {
        int s = __ldg(src + E - 1);
        int d = __ldg(dst + E - 1);
        const float4* va = (const float4*)(vals + (size_t)s * HIDDEN);
        float* oa = out + (size_t)d * HIDDEN;
#pragma unroll
        for (int j = 0; j < 4; j++) {
            float4 v = va[j];
            red_add_v4(oa + j * 4, v.x, v.y, v.z, v.w);
        }
    }
}

// h1 = relu((agg1 + z) * dinv + b1); store pre-scaled: g_h = h1 * dinv
__global__ void k_h1(const float* __restrict__ b1) {
    int t = blockIdx.x * blockDim.x + threadIdx.x;
    if (t >= N_NODES * 4) return;
    int i = t >> 2;
    int j = t & 3;
    float di = g_dinv[i];
    float4 a = ((const float4*)g_h)[t];
    float4 zz = ((const float4*)g_z)[t];
    float4 bb = __ldg((const float4*)b1 + j);
    float4 r;
    r.x = fmaxf(fmaf(a.x + zz.x, di, bb.x), 0.f) * di;
    r.y = fmaxf(fmaf(a.y + zz.y, di, bb.y), 0.f) * di;
    r.z = fmaxf(fmaf(a.z + zz.z, di, bb.z), 0.f) * di;
    r.w = fmaxf(fmaf(a.w + zz.w, di, bb.w), 0.f) * di;
    ((float4*)g_h)[t] = r;
}

// out = ((agg2 + h1s) * dinv) @ W2 + b2    (h1s = h1*dinv)
// 4 threads per row, each computes 16 output cols. W2 (4KB) in smem.
__global__ __launch_bounds__(256) void k_gemm2(const float* __restrict__ W2,
                                               const float* __restrict__ b2,
                                               float* __restrict__ out) {
    __shared__ __align__(16) float ws[HIDDEN * OUT_DIM];  // 1024 floats
    ((float4*)ws)[threadIdx.x] = ((const float4*)W2)[threadIdx.x];  // 256 float4
    __syncthreads();

    int gid = blockIdx.x * 256 + threadIdx.x;
    int r = gid >> 2;
    int cg = gid & 3;
    if (r >= N_NODES) return;

    float di = g_dinv[r];
    float hk[HIDDEN];
    const float4* A = (const float4*)(g_a2 + (size_t)r * HIDDEN);
    const float4* H = (const float4*)(g_h + (size_t)r * HIDDEN);
#pragma unroll
    for (int q = 0; q < 4; q++) {
        float4 a = A[q];
        float4 h = H[q];
        hk[4 * q + 0] = (a.x + h.x) * di;
        hk[4 * q + 1] = (a.y + h.y) * di;
        hk[4 * q + 2] = (a.z + h.z) * di;
        hk[4 * q + 3] = (a.w + h.w) * di;
    }

    float4 acc[4];
#pragma unroll
    for (int q = 0; q < 4; q++) acc[q] = make_float4(0.f, 0.f, 0.f, 0.f);

#pragma unroll
    for (int k = 0; k < HIDDEN; k++) {
        float xv = hk[k];
        const float4* wr = (const float4*)(ws + k * OUT_DIM + cg * 16);
#pragma unroll
        for (int q = 0; q < 4; q++) {
            float4 w = wr[q];
            acc[q].x = fmaf(xv, w.x, acc[q].x);
            acc[q].y = fmaf(xv, w.y, acc[q].y);
            acc[q].z = fmaf(xv, w.z, acc[q].z);
            acc[q].w = fmaf(xv, w.w, acc[q].w);
        }
    }

    const float4* bb = (const float4*)b2 + cg * 4;
    float4* O = (float4*)(out + (size_t)r * OUT_DIM) + cg * 4;
#pragma unroll
    for (int q = 0; q < 4; q++) {
        float4 b = __ldg(bb + q);
        O[q] = make_float4(acc[q].x + b.x, acc[q].y + b.y,
                           acc[q].z + b.z, acc[q].w + b.w);
    }
}

// ---------------- launch ----------------
extern "C" void kernel_launch(void* const* d_in, const int* in_sizes, int n_in,
                              void* d_out, int out_size) {
    const float* x = nullptr;
    const float* W1 = nullptr;
    const float* b1 = nullptr;
    const float* W2 = nullptr;
    const float* b2 = nullptr;
    const int* ei = nullptr;
    int E = 0;
    for (int i = 0; i < n_in; i++) {
        long long sz = in_sizes[i];
        if (sz == (long long)N_NODES * IN_DIM)      x  = (const float*)d_in[i];
        else if (sz == IN_DIM * HIDDEN)             W1 = (const float*)d_in[i];
        else if (sz == HIDDEN)                      b1 = (const float*)d_in[i];
        else if (sz == HIDDEN * OUT_DIM)            W2 = (const float*)d_in[i];
        else if (sz == OUT_DIM)                     b2 = (const float*)d_in[i];
        else { ei = (const int*)d_in[i]; E = (int)(sz / 2); }
    }
    const int* src = ei;
    const int* dst = ei + E;
    float* out = (float*)d_out;

    const int TB = 256;
    int E2 = E / 2;  // paired edges; odd tail handled in-kernel
    int grid_n4 = (N_NODES * 4 + TB - 1) / TB;
    int grid_n  = (N_NODES + TB - 1) / TB;
    int grid_e2 = (E2 + 1 + TB - 1) / TB;  // +1 slot for odd tail
    int grid_g1 = (N_NODES + 127) / 128;

    k_init<<<grid_n4, TB>>>();
    k_deg<<<grid_e2, TB>>>(dst, E2, E);
    k_dinv<<<grid_n, TB>>>();
    k_gemm1<<<grid_g1, 128>>>(x, W1);
    k_scatter<0><<<grid_e2, TB>>>(src, dst, E2, E);
    k_h1<<<grid_n4, TB>>>(b1);
    k_scatter<1><<<grid_e2, TB>>>(src, dst, E2, E);
    k_gemm2<<<grid_n4, TB>>>(W2, b2, out);
}

// round 4
// speedup vs baseline: 1.1219x; 1.0647x over previous
#include <cuda_runtime.h>

#define N_NODES 100000
#define IN_DIM 512
#define HIDDEN 16
#define OUT_DIM 64

// ---------------- device scratch (no allocations allowed) ----------------
__device__ __align__(16) float g_z[(size_t)N_NODES * HIDDEN];   // x@W1, pre-scaled by dinv[src]
__device__ __align__(16) float g_h[(size_t)N_NODES * HIDDEN];   // agg1 -> h1 (pre-scaled)
__device__ __align__(16) float g_a2[(size_t)N_NODES * HIDDEN];  // agg2
__device__ float g_deg[N_NODES];
__device__ float g_dinv[N_NODES];

// ---------------- helpers ----------------
__device__ __forceinline__ unsigned long long fma2(unsigned long long a,
                                                   unsigned long long b,
                                                   unsigned long long c) {
    unsigned long long d;
    asm("fma.rn.f32x2 %0, %1, %2, %3;" : "=l"(d) : "l"(a), "l"(b), "l"(c));
    return d;
}
__device__ __forceinline__ unsigned long long dup2(float v) {
    unsigned long long d;
    asm("mov.b64 %0, {%1, %2};" : "=l"(d) : "f"(v), "f"(v));
    return d;
}
__device__ __forceinline__ void red_add_v4(float* p, float a, float b, float c, float d) {
    asm volatile("red.global.add.v4.f32 [%0], {%1, %2, %3, %4};"
                 :: "l"(p), "f"(a), "f"(b), "f"(c), "f"(d) : "memory");
}
__device__ __forceinline__ void red_add_f32(float* p, float v) {
    asm volatile("red.global.add.f32 [%0], %1;" :: "l"(p), "f"(v) : "memory");
}

// ---------------- kernels ----------------

// zero agg buffers, deg = 1 (self loop)
__global__ void k_init() {
    int t = blockIdx.x * blockDim.x + threadIdx.x;
    float4 z4 = make_float4(0.f, 0.f, 0.f, 0.f);
    if (t < N_NODES * 4) {
        ((float4*)g_h)[t] = z4;
        ((float4*)g_a2)[t] = z4;
    }
    if (t < N_NODES) g_deg[t] = 1.0f;
}

// 4 edges per thread; tail handled by one guarded thread
__global__ void k_deg(const int* __restrict__ dst, int E4, int E) {
    int t = blockIdx.x * blockDim.x + threadIdx.x;
    if (t < E4) {
        int4 d = __ldg((const int4*)dst + t);
        red_add_f32(&g_deg[d.x], 1.0f);
        red_add_f32(&g_deg[d.y], 1.0f);
        red_add_f32(&g_deg[d.z], 1.0f);
        red_add_f32(&g_deg[d.w], 1.0f);
    } else if (t == E4) {
        for (int e = E4 * 4; e < E; e++)
            red_add_f32(&g_deg[__ldg(dst + e)], 1.0f);
    }
}

__global__ void k_dinv() {
    int i = blockIdx.x * blockDim.x + threadIdx.x;
    if (i < N_NODES) g_dinv[i] = rsqrtf(g_deg[i]);
}

// z = (x @ W1) * dinv[row].  128 threads/block, 4 rows/thread (strided by 128)
// -> 512 rows/block, 196 blocks. W1 (32KB) in smem; weight LDS amortized 4x.
__global__ __launch_bounds__(128) void k_gemm1(const float* __restrict__ x,
                                               const float* __restrict__ W1) {
    __shared__ __align__(16) float ws[IN_DIM * HIDDEN];  // 32 KB
    {
        const float4* w4 = (const float4*)W1;
        float4* s4 = (float4*)ws;
#pragma unroll
        for (int i = 0; i < (IN_DIM * HIDDEN / 4) / 128; i++)
            s4[threadIdx.x + i * 128] = w4[threadIdx.x + i * 128];
    }
    __syncthreads();

    long long base = (long long)blockIdx.x * 512 + threadIdx.x;
    long long r[4];
    const float4* xp[4];
#pragma unroll
    for (int i = 0; i < 4; i++) {
        r[i] = base + i * 128;
        long long ra = (r[i] < N_NODES) ? r[i] : 0;
        xp[i] = (const float4*)(x + ra * IN_DIM);
    }

    unsigned long long acc[4][8];
#pragma unroll
    for (int i = 0; i < 4; i++)
#pragma unroll
        for (int c = 0; c < 8; c++) acc[i][c] = 0ull;

    const ulonglong2* wsp = (const ulonglong2*)ws;  // row k = 4 x ulonglong2

#pragma unroll 1
    for (int q = 0; q < IN_DIM / 4; q += 2) {
        float4 xa[4], xb[4];
#pragma unroll
        for (int i = 0; i < 4; i++) xa[i] = xp[i][q];
#pragma unroll
        for (int i = 0; i < 4; i++) xb[i] = xp[i][q + 1];

#pragma unroll
        for (int j = 0; j < 4; j++) {
            int k = q * 4 + j;
            ulonglong2 w0 = wsp[k * 4 + 0];
            ulonglong2 w1 = wsp[k * 4 + 1];
            ulonglong2 w2 = wsp[k * 4 + 2];
            ulonglong2 w3 = wsp[k * 4 + 3];
#pragma unroll
            for (int i = 0; i < 4; i++) {
                unsigned long long d = dup2(((const float*)&xa[i])[j]);
                acc[i][0] = fma2(d, w0.x, acc[i][0]);
                acc[i][1] = fma2(d, w0.y, acc[i][1]);
                acc[i][2] = fma2(d, w1.x, acc[i][2]);
                acc[i][3] = fma2(d, w1.y, acc[i][3]);
                acc[i][4] = fma2(d, w2.x, acc[i][4]);
                acc[i][5] = fma2(d, w2.y, acc[i][5]);
                acc[i][6] = fma2(d, w3.x, acc[i][6]);
                acc[i][7] = fma2(d, w3.y, acc[i][7]);
            }
        }
#pragma unroll
        for (int j = 0; j < 4; j++) {
            int k = (q + 1) * 4 + j;
            ulonglong2 w0 = wsp[k * 4 + 0];
            ulonglong2 w1 = wsp[k * 4 + 1];
            ulonglong2 w2 = wsp[k * 4 + 2];
            ulonglong2 w3 = wsp[k * 4 + 3];
#pragma unroll
            for (int i = 0; i < 4; i++) {
                unsigned long long d = dup2(((const float*)&xb[i])[j]);
                acc[i][0] = fma2(d, w0.x, acc[i][0]);
                acc[i][1] = fma2(d, w0.y, acc[i][1]);
                acc[i][2] = fma2(d, w1.x, acc[i][2]);
                acc[i][3] = fma2(d, w1.y, acc[i][3]);
                acc[i][4] = fma2(d, w2.x, acc[i][4]);
                acc[i][5] = fma2(d, w2.y, acc[i][5]);
                acc[i][6] = fma2(d, w3.x, acc[i][6]);
                acc[i][7] = fma2(d, w3.y, acc[i][7]);
            }
        }
    }

#pragma unroll
    for (int i = 0; i < 4; i++) {
        if (r[i] < N_NODES) {
            float dv = g_dinv[r[i]];
            float2* zo = (float2*)(g_z + r[i] * HIDDEN);
#pragma unroll
            for (int c = 0; c < 8; c++) {
                float2 p = *(float2*)&acc[i][c];
                p.x *= dv; p.y *= dv;
                zo[c] = p;
            }
        }
    }
}

// edge scatter: out[dst] += vals[src]   (vals pre-scaled by dinv[src];
// dinv[dst] folded into the following per-node pass). 4 edges/thread.
template <int LAYER>
__global__ __launch_bounds__(256) void k_scatter(const int* __restrict__ src,
                                                 const int* __restrict__ dst,
                                                 int E4, int E) {
    int t = blockIdx.x * blockDim.x + threadIdx.x;
    const float* vals = (LAYER == 0) ? g_z : g_h;
    float* out = (LAYER == 0) ? g_h : g_a2;

    if (t < E4) {
        int4 s = __ldg((const int4*)src + t);
        int4 d = __ldg((const int4*)dst + t);
        const int sv[4] = {s.x, s.y, s.z, s.w};
        const int dv[4] = {d.x, d.y, d.z, d.w};
        float4 v[4][4];
#pragma unroll
        for (int e = 0; e < 4; e++) {
            const float4* vp = (const float4*)(vals + (size_t)sv[e] * HIDDEN);
#pragma unroll
            for (int j = 0; j < 4; j++) v[e][j] = vp[j];
        }
#pragma unroll
        for (int e = 0; e < 4; e++) {
            float* o = out + (size_t)dv[e] * HIDDEN;
#pragma unroll
            for (int j = 0; j < 4; j++)
                red_add_v4(o + j * 4, v[e][j].x, v[e][j].y, v[e][j].z, v[e][j].w);
        }
    } else if (t == E4) {
        for (int e = E4 * 4; e < E; e++) {
            int s = __ldg(src + e);
            int d = __ldg(dst + e);
            const float4* vp = (const float4*)(vals + (size_t)s * HIDDEN);
            float* o = out + (size_t)d * HIDDEN;
#pragma unroll
            for (int j = 0; j < 4; j++) {
                float4 vv = vp[j];
                red_add_v4(o + j * 4, vv.x, vv.y, vv.z, vv.w);
            }
        }
    }
}

// h1 = relu((agg1 + z) * dinv + b1); store pre-scaled: g_h = h1 * dinv
__global__ void k_h1(const float* __restrict__ b1) {
    int t = blockIdx.x * blockDim.x + threadIdx.x;
    if (t >= N_NODES * 4) return;
    int i = t >> 2;
    int j = t & 3;
    float di = g_dinv[i];
    float4 a = ((const float4*)g_h)[t];
    float4 zz = ((const float4*)g_z)[t];
    float4 bb = __ldg((const float4*)b1 + j);
    float4 r;
    r.x = fmaxf(fmaf(a.x + zz.x, di, bb.x), 0.f) * di;
    r.y = fmaxf(fmaf(a.y + zz.y, di, bb.y), 0.f) * di;
    r.z = fmaxf(fmaf(a.z + zz.z, di, bb.z), 0.f) * di;
    r.w = fmaxf(fmaf(a.w + zz.w, di, bb.w), 0.f) * di;
    ((float4*)g_h)[t] = r;
}

// out = ((agg2 + h1s) * dinv) @ W2 + b2    (h1s = h1*dinv)
// 4 threads per row, each computes 16 output cols. W2 (4KB) in smem.
__global__ __launch_bounds__(256) void k_gemm2(const float* __restrict__ W2,
                                               const float* __restrict__ b2,
                                               float* __restrict__ out) {
    __shared__ __align__(16) float ws[HIDDEN * OUT_DIM];  // 1024 floats
    ((float4*)ws)[threadIdx.x] = ((const float4*)W2)[threadIdx.x];  // 256 float4
    __syncthreads();

    int gid = blockIdx.x * 256 + threadIdx.x;
    int r = gid >> 2;
    int cg = gid & 3;
    if (r >= N_NODES) return;

    float di = g_dinv[r];
    float hk[HIDDEN];
    const float4* A = (const float4*)(g_a2 + (size_t)r * HIDDEN);
    const float4* H = (const float4*)(g_h + (size_t)r * HIDDEN);
#pragma unroll
    for (int q = 0; q < 4; q++) {
        float4 a = A[q];
        float4 h = H[q];
        hk[4 * q + 0] = (a.x + h.x) * di;
        hk[4 * q + 1] = (a.y + h.y) * di;
        hk[4 * q + 2] = (a.z + h.z) * di;
        hk[4 * q + 3] = (a.w + h.w) * di;
    }

    float4 acc[4];
#pragma unroll
    for (int q = 0; q < 4; q++) acc[q] = make_float4(0.f, 0.f, 0.f, 0.f);

#pragma unroll
    for (int k = 0; k < HIDDEN; k++) {
        float xv = hk[k];
        const float4* wr = (const float4*)(ws + k * OUT_DIM + cg * 16);
#pragma unroll
        for (int q = 0; q < 4; q++) {
            float4 w = wr[q];
            acc[q].x = fmaf(xv, w.x, acc[q].x);
            acc[q].y = fmaf(xv, w.y, acc[q].y);
            acc[q].z = fmaf(xv, w.z, acc[q].z);
            acc[q].w = fmaf(xv, w.w, acc[q].w);
        }
    }

    const float4* bb = (const float4*)b2 + cg * 4;
    float4* O = (float4*)(out + (size_t)r * OUT_DIM) + cg * 4;
#pragma unroll
    for (int q = 0; q < 4; q++) {
        float4 b = __ldg(bb + q);
        O[q] = make_float4(acc[q].x + b.x, acc[q].y + b.y,
                           acc[q].z + b.z, acc[q].w + b.w);
    }
}

// ---------------- launch ----------------
extern "C" void kernel_launch(void* const* d_in, const int* in_sizes, int n_in,
                              void* d_out, int out_size) {
    const float* x = nullptr;
    const float* W1 = nullptr;
    const float* b1 = nullptr;
    const float* W2 = nullptr;
    const float* b2 = nullptr;
    const int* ei = nullptr;
    int E = 0;
    for (int i = 0; i < n_in; i++) {
        long long sz = in_sizes[i];
        if (sz == (long long)N_NODES * IN_DIM)      x  = (const float*)d_in[i];
        else if (sz == IN_DIM * HIDDEN)             W1 = (const float*)d_in[i];
        else if (sz == HIDDEN)                      b1 = (const float*)d_in[i];
        else if (sz == HIDDEN * OUT_DIM)            W2 = (const float*)d_in[i];
        else if (sz == OUT_DIM)                     b2 = (const float*)d_in[i];
        else { ei = (const int*)d_in[i]; E = (int)(sz / 2); }
    }
    const int* src = ei;
    const int* dst = ei + E;
    float* out = (float*)d_out;

    const int TB = 256;
    int E4 = E / 4;  // 4 edges/thread; tail in-kernel
    int grid_n4 = (N_NODES * 4 + TB - 1) / TB;
    int grid_n  = (N_NODES + TB - 1) / TB;
    int grid_e4 = (E4 + 1 + TB - 1) / TB;  // +1 slot for tail thread
    int grid_g1 = (N_NODES + 511) / 512;

    k_init<<<grid_n4, TB>>>();
    k_deg<<<grid_e4, TB>>>(dst, E4, E);
    k_dinv<<<grid_n, TB>>>();
    k_gemm1<<<grid_g1, 128>>>(x, W1);
    k_scatter<0><<<grid_e4, TB>>>(src, dst, E4, E);
    k_h1<<<grid_n4, TB>>>(b1);
    k_scatter<1><<<grid_e4, TB>>>(src, dst, E4, E);
    k_gemm2<<<grid_n4, TB>>>(W2, b2, out);
}